// round 1
// baseline (speedup 1.0000x reference)
#include <cuda_runtime.h>
#include <cstddef>

#define B_ 4
#define T_ 2048
#define E_ 1024
#define H_ 16
#define D_ 64

// Scratch: q,k,v in [B,H,T,D]; att in [B,T,H*D]. 32MB each.
__device__ float g_q[(size_t)B_ * H_ * T_ * D_];
__device__ float g_k[(size_t)B_ * H_ * T_ * D_];
__device__ float g_v[(size_t)B_ * H_ * T_ * D_];
__device__ float g_att[(size_t)B_ * T_ * H_ * D_];

// ---------------------------------------------------------------------------
// Kernel 1: QKV projection. For each (b,h,which): out = x[b] (2048x1024) @ W[h] (1024x64)
// Tiles: BM=64 (t), BN=64 (full D), BK=32 (e). 256 threads, 4x4 per thread.
// ---------------------------------------------------------------------------
__global__ __launch_bounds__(256) void qkv_kernel(
    const float* __restrict__ x,
    const float* __restrict__ Wq,
    const float* __restrict__ Wk,
    const float* __restrict__ Wv) {
    __shared__ float sX[64][33];
    __shared__ float sW[32][64];

    const int mt = blockIdx.x;        // 0..31  (T/64)
    const int bh = blockIdx.y;        // b*16+h
    const int which = blockIdx.z;     // 0=q 1=k 2=v
    const int b = bh >> 4, h = bh & 15;

    const float* W = (which == 0 ? Wq : (which == 1 ? Wk : Wv)) + (size_t)h * E_ * D_;
    float* out = (which == 0 ? g_q : (which == 1 ? g_k : g_v)) + ((size_t)bh * T_ + (size_t)mt * 64) * D_;
    const float* X = x + ((size_t)b * T_ + (size_t)mt * 64) * E_;

    const int tid = threadIdx.x;
    const int tx = tid & 15, ty = tid >> 4;

    float acc[4][4] = {};

    for (int k0 = 0; k0 < E_; k0 += 32) {
        __syncthreads();
#pragma unroll
        for (int i = 0; i < 8; i++) {
            int lin = tid + i * 256;
            int r = lin >> 5, c = lin & 31;
            sX[r][c] = X[(size_t)r * E_ + k0 + c];
        }
#pragma unroll
        for (int i = 0; i < 8; i++) {
            int lin = tid + i * 256;
            int r = lin >> 6, c = lin & 63;
            sW[r][c] = W[(size_t)(k0 + r) * D_ + c];
        }
        __syncthreads();
#pragma unroll
        for (int kk = 0; kk < 32; kk++) {
            float a[4], w[4];
#pragma unroll
            for (int i = 0; i < 4; i++) a[i] = sX[ty * 4 + i][kk];
#pragma unroll
            for (int j = 0; j < 4; j++) w[j] = sW[kk][tx * 4 + j];
#pragma unroll
            for (int i = 0; i < 4; i++)
#pragma unroll
                for (int j = 0; j < 4; j++) acc[i][j] += a[i] * w[j];
        }
    }

#pragma unroll
    for (int i = 0; i < 4; i++)
#pragma unroll
        for (int j = 0; j < 4; j++)
            out[(ty * 4 + i) * D_ + tx * 4 + j] = acc[i][j];
}

// ---------------------------------------------------------------------------
// Kernel 2: causal flash attention. One CTA per (q-tile qi, b*h).
// 64x64 tiles, D=64 fully resident. Online softmax; key loop runs j<=qi only.
// Dynamic smem: sQ,sK,sV,sS (64x65 each) + sM,sL,sAlpha (64 each) = 67328 B.
// ---------------------------------------------------------------------------
__global__ __launch_bounds__(256) void attn_kernel() {
    extern __shared__ float sm[];
    float* sQ = sm;                 // 64*65
    float* sK = sQ + 64 * 65;
    float* sV = sK + 64 * 65;
    float* sS = sV + 64 * 65;
    float* sM = sS + 64 * 65;       // 64
    float* sL = sM + 64;            // 64
    float* sAl = sL + 64;           // 64

    const int qi = blockIdx.x;      // 0..31
    const int bh = blockIdx.y;      // 0..63
    const int tid = threadIdx.x;
    const int tx = tid & 15, ty = tid >> 4;
    const int row = tid >> 2, part = tid & 3;   // softmax mapping: 4 lanes per row
    const float scale = 0.125f;     // 1/sqrt(64)

    const float* Qb = g_q + ((size_t)bh * T_ + (size_t)qi * 64) * D_;
    const float* Kb = g_k + (size_t)bh * T_ * D_;
    const float* Vb = g_v + (size_t)bh * T_ * D_;

    // load Q tile (64x64)
#pragma unroll
    for (int i = 0; i < 16; i++) {
        int lin = tid + i * 256;
        int r = lin >> 6, c = lin & 63;
        sQ[r * 65 + c] = Qb[(size_t)r * D_ + c];
    }
    if (tid < 64) { sM[tid] = -1e30f; sL[tid] = 0.f; }

    float accO[4][4] = {};

    for (int j = 0; j <= qi; j++) {
        __syncthreads();   // protect sK/sV/sS of previous iter
        const float* Kj = Kb + (size_t)j * 64 * D_;
        const float* Vj = Vb + (size_t)j * 64 * D_;
#pragma unroll
        for (int i = 0; i < 16; i++) {
            int lin = tid + i * 256;
            int r = lin >> 6, c = lin & 63;
            sK[r * 65 + c] = Kj[(size_t)r * D_ + c];
            sV[r * 65 + c] = Vj[(size_t)r * D_ + c];
        }
        __syncthreads();

        // S = scale * Q K^T  (4x4 per thread)
        float s[4][4] = {};
#pragma unroll
        for (int d = 0; d < 64; d++) {
            float a[4], bk[4];
#pragma unroll
            for (int i = 0; i < 4; i++) a[i] = sQ[(ty * 4 + i) * 65 + d];
#pragma unroll
            for (int jj = 0; jj < 4; jj++) bk[jj] = sK[(tx * 4 + jj) * 65 + d];
#pragma unroll
            for (int i = 0; i < 4; i++)
#pragma unroll
                for (int jj = 0; jj < 4; jj++) s[i][jj] += a[i] * bk[jj];
        }
        const bool diag = (j == qi);
#pragma unroll
        for (int i = 0; i < 4; i++) {
#pragma unroll
            for (int jj = 0; jj < 4; jj++) {
                float v = s[i][jj] * scale;
                if (diag && (tx * 4 + jj) > (ty * 4 + i)) v = -1e30f;
                sS[(ty * 4 + i) * 65 + tx * 4 + jj] = v;
            }
        }
        __syncthreads();

        // online softmax: 4 lanes per row, shuffle-reduce
        float pmax = -1e30f;
#pragma unroll
        for (int cc = 0; cc < 16; cc++)
            pmax = fmaxf(pmax, sS[row * 65 + part * 16 + cc]);
        pmax = fmaxf(pmax, __shfl_xor_sync(0xffffffffu, pmax, 1));
        pmax = fmaxf(pmax, __shfl_xor_sync(0xffffffffu, pmax, 2));
        float m_old = sM[row];
        float m_new = fmaxf(m_old, pmax);
        float psum = 0.f;
#pragma unroll
        for (int cc = 0; cc < 16; cc++) {
            int c = part * 16 + cc;
            float p = __expf(sS[row * 65 + c] - m_new);
            sS[row * 65 + c] = p;
            psum += p;
        }
        psum += __shfl_xor_sync(0xffffffffu, psum, 1);
        psum += __shfl_xor_sync(0xffffffffu, psum, 2);
        if (part == 0) {
            float al = __expf(m_old - m_new);
            sAl[row] = al;
            sM[row] = m_new;
            sL[row] = sL[row] * al + psum;
        }
        __syncthreads();

        // rescale accumulator and accumulate P @ V
#pragma unroll
        for (int i = 0; i < 4; i++) {
            float al = sAl[ty * 4 + i];
#pragma unroll
            for (int jj = 0; jj < 4; jj++) accO[i][jj] *= al;
        }
#pragma unroll
        for (int ss = 0; ss < 64; ss++) {
            float p[4], bv[4];
#pragma unroll
            for (int i = 0; i < 4; i++) p[i] = sS[(ty * 4 + i) * 65 + ss];
#pragma unroll
            for (int jj = 0; jj < 4; jj++) bv[jj] = sV[ss * 65 + tx * 4 + jj];
#pragma unroll
            for (int i = 0; i < 4; i++)
#pragma unroll
                for (int jj = 0; jj < 4; jj++) accO[i][jj] += p[i] * bv[jj];
        }
    }
    __syncthreads();

    // normalize and write: att layout [B, T, H*D]
    const int b = bh >> 4, h = bh & 15;
    float linv[4];
#pragma unroll
    for (int i = 0; i < 4; i++) linv[i] = 1.f / sL[ty * 4 + i];
    float* Ob = g_att + ((size_t)b * T_ + (size_t)qi * 64) * (H_ * D_) + h * D_;
#pragma unroll
    for (int i = 0; i < 4; i++)
#pragma unroll
        for (int jj = 0; jj < 4; jj++)
            Ob[(size_t)(ty * 4 + i) * (H_ * D_) + tx * 4 + jj] = accO[i][jj] * linv[i];
}

// ---------------------------------------------------------------------------
// Kernel 3: output projection + bias.
// C[8192,1024] = att[8192,1024] @ Wproj[1024,1024] + bproj
// Tiles: BM=64, BN=64, BK=32. 256 threads, 4x4 per thread.
// ---------------------------------------------------------------------------
__global__ __launch_bounds__(256) void proj_kernel(
    const float* __restrict__ Wp,
    const float* __restrict__ bias,
    float* __restrict__ C) {
    __shared__ float sA[64][33];
    __shared__ float sB[32][64];

    const int mt = blockIdx.x;  // 0..127
    const int nt = blockIdx.y;  // 0..15
    const int tid = threadIdx.x;
    const int tx = tid & 15, ty = tid >> 4;

    const float* A = g_att + (size_t)mt * 64 * (H_ * D_);
    const float* Bw = Wp + (size_t)nt * 64;

    float acc[4][4] = {};

    for (int k0 = 0; k0 < H_ * D_; k0 += 32) {
        __syncthreads();
#pragma unroll
        for (int i = 0; i < 8; i++) {
            int lin = tid + i * 256;
            int r = lin >> 5, c = lin & 31;
            sA[r][c] = A[(size_t)r * (H_ * D_) + k0 + c];
        }
#pragma unroll
        for (int i = 0; i < 8; i++) {
            int lin = tid + i * 256;
            int r = lin >> 6, c = lin & 63;
            sB[r][c] = Bw[(size_t)(k0 + r) * E_ + c];
        }
        __syncthreads();
#pragma unroll
        for (int kk = 0; kk < 32; kk++) {
            float a[4], w[4];
#pragma unroll
            for (int i = 0; i < 4; i++) a[i] = sA[ty * 4 + i][kk];
#pragma unroll
            for (int j = 0; j < 4; j++) w[j] = sB[kk][tx * 4 + j];
#pragma unroll
            for (int i = 0; i < 4; i++)
#pragma unroll
                for (int j = 0; j < 4; j++) acc[i][j] += a[i] * w[j];
        }
    }

    float* Cb = C + (size_t)mt * 64 * E_ + (size_t)nt * 64;
#pragma unroll
    for (int i = 0; i < 4; i++) {
#pragma unroll
        for (int j = 0; j < 4; j++) {
            Cb[(size_t)(ty * 4 + i) * E_ + tx * 4 + j] = acc[i][j] + bias[nt * 64 + tx * 4 + j];
        }
    }
}

// ---------------------------------------------------------------------------
extern "C" void kernel_launch(void* const* d_in, const int* in_sizes, int n_in,
                              void* d_out, int out_size) {
    const float* x     = (const float*)d_in[0];
    const float* Wq    = (const float*)d_in[1];
    const float* Wk    = (const float*)d_in[2];
    const float* Wv    = (const float*)d_in[3];
    const float* Wproj = (const float*)d_in[4];
    const float* bproj = (const float*)d_in[5];
    float* out = (float*)d_out;

    // QKV projections: 32 M-tiles x 64 (b,h) x {q,k,v}
    qkv_kernel<<<dim3(32, 64, 3), 256>>>(x, Wq, Wk, Wv);

    // flash attention: 32 q-tiles x 64 (b,h)
    const int attn_smem = (4 * 64 * 65 + 3 * 64) * (int)sizeof(float);  // 67328 B
    cudaFuncSetAttribute(attn_kernel, cudaFuncAttributeMaxDynamicSharedMemorySize, attn_smem);
    attn_kernel<<<dim3(32, 64), 256, attn_smem>>>();

    // output projection: 128 M-tiles x 16 N-tiles
    proj_kernel<<<dim3(128, 16), 256>>>(Wproj, bproj, out);
}

// round 2
// speedup vs baseline: 2.7952x; 2.7952x over previous
#include <cuda_runtime.h>
#include <cstdint>
#include <cstddef>

#define B_ 4
#define T_ 2048
#define E_ 1024
#define H_ 16
#define D_ 64

// Scratch: q,k,v in [B,H,T,D]; att in [B,T,H*D]. 32MB each.
__device__ float g_q[(size_t)B_ * H_ * T_ * D_];
__device__ float g_k[(size_t)B_ * H_ * T_ * D_];
__device__ float g_v[(size_t)B_ * H_ * T_ * D_];
__device__ float g_att[(size_t)B_ * T_ * H_ * D_];

__device__ __forceinline__ uint32_t f2tf(float f) {
    uint32_t r;
    asm("cvt.rna.tf32.f32 %0, %1;" : "=r"(r) : "f"(f));
    return r;
}

__device__ __forceinline__ void mma_tf32(float c[4], const uint32_t a[4], const uint32_t b[2]) {
    asm volatile(
        "mma.sync.aligned.m16n8k8.row.col.f32.tf32.tf32.f32 "
        "{%0,%1,%2,%3}, {%4,%5,%6,%7}, {%8,%9}, {%0,%1,%2,%3};"
        : "+f"(c[0]), "+f"(c[1]), "+f"(c[2]), "+f"(c[3])
        : "r"(a[0]), "r"(a[1]), "r"(a[2]), "r"(a[3]), "r"(b[0]), "r"(b[1]));
}

// ---------------------------------------------------------------------------
// Kernel 1: fused QKV GEMM.  C[8192, 3072] = X[8192,1024] @ Wcat[1024,3072]
// N-tile of 64 == one (which, head). CTA: BM=128, BN=64, BK=32, 256 thr.
// 8 warps as 4(M)x2(N), warp tile 32x32.
// ---------------------------------------------------------------------------
__global__ __launch_bounds__(256) void qkv_mma_kernel(
    const float* __restrict__ x,
    const float* __restrict__ Wq,
    const float* __restrict__ Wk,
    const float* __restrict__ Wv) {
    __shared__ uint32_t sA[128 * 36];   // stride 36 (== 4 mod 32)
    __shared__ uint32_t sB[32 * 72];    // stride 72 (== 8 mod 32)

    const int mt = blockIdx.x;          // 0..63
    const int nt = blockIdx.y;          // 0..47
    const int which = nt >> 4, h = nt & 15;

    const float* W = (which == 0 ? Wq : (which == 1 ? Wk : Wv)) + (size_t)h * E_ * D_;
    float* outsel = (which == 0 ? g_q : (which == 1 ? g_k : g_v));

    const int tid = threadIdx.x;
    const int w = tid >> 5, lane = tid & 31;
    const int wm = w >> 1, wn = w & 1;
    const int m0 = wm * 32, n0 = wn * 32;
    const int lr = lane >> 2, lc = lane & 3;

    const float* Xb = x + (size_t)mt * 128 * E_;

    float acc[2][4][4];
#pragma unroll
    for (int mi = 0; mi < 2; mi++)
#pragma unroll
        for (int ni = 0; ni < 4; ni++)
#pragma unroll
            for (int rr = 0; rr < 4; rr++) acc[mi][ni][rr] = 0.f;

    for (int k0 = 0; k0 < E_; k0 += 32) {
        // A: 128x32, 4 float4 per thread
#pragma unroll
        for (int l = 0; l < 4; l++) {
            int idx = tid + l * 256;
            int r = idx >> 3, c4 = (idx & 7) * 4;
            float4 v = *reinterpret_cast<const float4*>(Xb + (size_t)r * E_ + k0 + c4);
            sA[r * 36 + c4 + 0] = f2tf(v.x);
            sA[r * 36 + c4 + 1] = f2tf(v.y);
            sA[r * 36 + c4 + 2] = f2tf(v.z);
            sA[r * 36 + c4 + 3] = f2tf(v.w);
        }
        // B: 32x64, 2 float4 per thread
#pragma unroll
        for (int l = 0; l < 2; l++) {
            int idx = tid + l * 256;
            int r = idx >> 4, c4 = (idx & 15) * 4;
            float4 v = *reinterpret_cast<const float4*>(W + (size_t)(k0 + r) * D_ + c4);
            sB[r * 72 + c4 + 0] = f2tf(v.x);
            sB[r * 72 + c4 + 1] = f2tf(v.y);
            sB[r * 72 + c4 + 2] = f2tf(v.z);
            sB[r * 72 + c4 + 3] = f2tf(v.w);
        }
        __syncthreads();

#pragma unroll
        for (int ks = 0; ks < 32; ks += 8) {
            uint32_t a[2][4], b[4][2];
#pragma unroll
            for (int mi = 0; mi < 2; mi++) {
                int r0 = m0 + 16 * mi + lr;
                a[mi][0] = sA[r0 * 36 + ks + lc];
                a[mi][1] = sA[(r0 + 8) * 36 + ks + lc];
                a[mi][2] = sA[r0 * 36 + ks + 4 + lc];
                a[mi][3] = sA[(r0 + 8) * 36 + ks + 4 + lc];
            }
#pragma unroll
            for (int ni = 0; ni < 4; ni++) {
                int cb = n0 + 8 * ni + lr;
                b[ni][0] = sB[(ks + lc) * 72 + cb];
                b[ni][1] = sB[(ks + 4 + lc) * 72 + cb];
            }
#pragma unroll
            for (int mi = 0; mi < 2; mi++)
#pragma unroll
                for (int ni = 0; ni < 4; ni++) mma_tf32(acc[mi][ni], a[mi], b[ni]);
        }
        __syncthreads();
    }

    // epilogue: tile never crosses batch boundary (2048 % 128 == 0)
    const int b_ = (mt * 128) / T_;
    const int tbase = (mt * 128) % T_ + m0;
    float* O = outsel + ((size_t)(b_ * H_ + h) * T_ + tbase) * D_;
#pragma unroll
    for (int mi = 0; mi < 2; mi++)
#pragma unroll
        for (int ni = 0; ni < 4; ni++)
#pragma unroll
            for (int rr = 0; rr < 4; rr++) {
                int row = 16 * mi + lr + (rr >= 2 ? 8 : 0);
                int col = n0 + 8 * ni + lc * 2 + (rr & 1);
                O[(size_t)row * D_ + col] = acc[mi][ni][rr];
            }
}

// ---------------------------------------------------------------------------
// Kernel 2: causal flash attention with tensor-core matmuls.
// 64x64 tiles, 256 thr = 8 warps as 2(M)x4(N), warp tile 32x16.
// sQ,sK,sS stride 68; sV stride 72. Softmax fp32 in smem; P rounded to tf32.
// ---------------------------------------------------------------------------
__global__ __launch_bounds__(256) void attn_mma_kernel() {
    extern __shared__ uint32_t sm[];
    uint32_t* sQ = sm;                    // 64*68
    uint32_t* sK = sQ + 64 * 68;          // 64*68
    uint32_t* sV = sK + 64 * 68;          // 64*72
    float* sS = reinterpret_cast<float*>(sV + 64 * 72);  // 64*68
    float* sM = sS + 64 * 68;
    float* sL = sM + 64;
    float* sAl = sL + 64;

    const int qi = blockIdx.x;            // 0..31
    const int bh = blockIdx.y;            // 0..63
    const int tid = threadIdx.x;
    const int w = tid >> 5, lane = tid & 31;
    const int wm = w >> 2, wn = w & 3;    // 2 x 4 warps
    const int m0 = wm * 32, n0 = wn * 16;
    const int lr = lane >> 2, lc = lane & 3;
    const int row = tid >> 2, part = tid & 3;  // softmax mapping
    const float scale = 0.125f;

    const float* Qb = g_q + ((size_t)bh * T_ + (size_t)qi * 64) * D_;
    const float* Kb = g_k + (size_t)bh * T_ * D_;
    const float* Vb = g_v + (size_t)bh * T_ * D_;

    // Q tile (tf32)
#pragma unroll
    for (int l = 0; l < 4; l++) {
        int idx = tid + l * 256;
        int r = idx >> 4, c4 = (idx & 15) * 4;
        float4 v = *reinterpret_cast<const float4*>(Qb + (size_t)r * D_ + c4);
        sQ[r * 68 + c4 + 0] = f2tf(v.x);
        sQ[r * 68 + c4 + 1] = f2tf(v.y);
        sQ[r * 68 + c4 + 2] = f2tf(v.z);
        sQ[r * 68 + c4 + 3] = f2tf(v.w);
    }
    if (tid < 64) { sM[tid] = -1e30f; sL[tid] = 0.f; }

    float o[2][2][4];
#pragma unroll
    for (int mi = 0; mi < 2; mi++)
#pragma unroll
        for (int ni = 0; ni < 2; ni++)
#pragma unroll
            for (int rr = 0; rr < 4; rr++) o[mi][ni][rr] = 0.f;

    for (int j = 0; j <= qi; j++) {
        __syncthreads();
        const float* Kj = Kb + (size_t)j * 64 * D_;
        const float* Vj = Vb + (size_t)j * 64 * D_;
#pragma unroll
        for (int l = 0; l < 4; l++) {
            int idx = tid + l * 256;
            int r = idx >> 4, c4 = (idx & 15) * 4;
            float4 vk = *reinterpret_cast<const float4*>(Kj + (size_t)r * D_ + c4);
            float4 vv = *reinterpret_cast<const float4*>(Vj + (size_t)r * D_ + c4);
            sK[r * 68 + c4 + 0] = f2tf(vk.x);
            sK[r * 68 + c4 + 1] = f2tf(vk.y);
            sK[r * 68 + c4 + 2] = f2tf(vk.z);
            sK[r * 68 + c4 + 3] = f2tf(vk.w);
            sV[r * 72 + c4 + 0] = f2tf(vv.x);
            sV[r * 72 + c4 + 1] = f2tf(vv.y);
            sV[r * 72 + c4 + 2] = f2tf(vv.z);
            sV[r * 72 + c4 + 3] = f2tf(vv.w);
        }
        __syncthreads();

        // S = Q K^T  (warp tile 32x16)
        float s[2][2][4];
#pragma unroll
        for (int mi = 0; mi < 2; mi++)
#pragma unroll
            for (int ni = 0; ni < 2; ni++)
#pragma unroll
                for (int rr = 0; rr < 4; rr++) s[mi][ni][rr] = 0.f;
#pragma unroll
        for (int ks = 0; ks < 64; ks += 8) {
            uint32_t a[2][4], b[2][2];
#pragma unroll
            for (int mi = 0; mi < 2; mi++) {
                int r0 = m0 + 16 * mi + lr;
                a[mi][0] = sQ[r0 * 68 + ks + lc];
                a[mi][1] = sQ[(r0 + 8) * 68 + ks + lc];
                a[mi][2] = sQ[r0 * 68 + ks + 4 + lc];
                a[mi][3] = sQ[(r0 + 8) * 68 + ks + 4 + lc];
            }
#pragma unroll
            for (int ni = 0; ni < 2; ni++) {
                int nb = n0 + 8 * ni + lr;   // key row
                b[ni][0] = sK[nb * 68 + ks + lc];
                b[ni][1] = sK[nb * 68 + ks + 4 + lc];
            }
#pragma unroll
            for (int mi = 0; mi < 2; mi++)
#pragma unroll
                for (int ni = 0; ni < 2; ni++) mma_tf32(s[mi][ni], a[mi], b[ni]);
        }

        // store scaled+masked S
        const bool diag = (j == qi);
#pragma unroll
        for (int mi = 0; mi < 2; mi++)
#pragma unroll
            for (int ni = 0; ni < 2; ni++)
#pragma unroll
                for (int rr = 0; rr < 4; rr++) {
                    int r = m0 + 16 * mi + lr + (rr >= 2 ? 8 : 0);
                    int c = n0 + 8 * ni + lc * 2 + (rr & 1);
                    float v = s[mi][ni][rr] * scale;
                    if (diag && c > r) v = -1e30f;
                    sS[r * 68 + c] = v;
                }
        __syncthreads();

        // online softmax (4 lanes per row)
        float pmax = -1e30f;
#pragma unroll
        for (int cc = 0; cc < 16; cc++)
            pmax = fmaxf(pmax, sS[row * 68 + part * 16 + cc]);
        pmax = fmaxf(pmax, __shfl_xor_sync(0xffffffffu, pmax, 1));
        pmax = fmaxf(pmax, __shfl_xor_sync(0xffffffffu, pmax, 2));
        float m_old = sM[row];
        float m_new = fmaxf(m_old, pmax);
        float psum = 0.f;
#pragma unroll
        for (int cc = 0; cc < 16; cc++) {
            int c = part * 16 + cc;
            float p = __expf(sS[row * 68 + c] - m_new);
            uint32_t pt = f2tf(p);               // consistent with mma's operand
            float pr = __uint_as_float(pt);
            sS[row * 68 + c] = pr;
            psum += pr;
        }
        psum += __shfl_xor_sync(0xffffffffu, psum, 1);
        psum += __shfl_xor_sync(0xffffffffu, psum, 2);
        if (part == 0) {
            float al = __expf(m_old - m_new);
            sAl[row] = al;
            sM[row] = m_new;
            sL[row] = sL[row] * al + psum;
        }
        __syncthreads();

        // rescale O and accumulate P @ V
#pragma unroll
        for (int mi = 0; mi < 2; mi++) {
            float al0 = sAl[m0 + 16 * mi + lr];
            float al1 = sAl[m0 + 16 * mi + 8 + lr];
#pragma unroll
            for (int ni = 0; ni < 2; ni++) {
                o[mi][ni][0] *= al0;
                o[mi][ni][1] *= al0;
                o[mi][ni][2] *= al1;
                o[mi][ni][3] *= al1;
            }
        }
#pragma unroll
        for (int ks = 0; ks < 64; ks += 8) {
            uint32_t a[2][4], b[2][2];
#pragma unroll
            for (int mi = 0; mi < 2; mi++) {
                int r0 = m0 + 16 * mi + lr;
                a[mi][0] = __float_as_uint(sS[r0 * 68 + ks + lc]);
                a[mi][1] = __float_as_uint(sS[(r0 + 8) * 68 + ks + lc]);
                a[mi][2] = __float_as_uint(sS[r0 * 68 + ks + 4 + lc]);
                a[mi][3] = __float_as_uint(sS[(r0 + 8) * 68 + ks + 4 + lc]);
            }
#pragma unroll
            for (int ni = 0; ni < 2; ni++) {
                int nb = n0 + 8 * ni + lr;   // d index
                b[ni][0] = sV[(ks + lc) * 72 + nb];
                b[ni][1] = sV[(ks + 4 + lc) * 72 + nb];
            }
#pragma unroll
            for (int mi = 0; mi < 2; mi++)
#pragma unroll
                for (int ni = 0; ni < 2; ni++) mma_tf32(o[mi][ni], a[mi], b[ni]);
        }
    }
    __syncthreads();

    // normalize & write: att layout [B, T, H*D]
    const int b_ = bh >> 4, h = bh & 15;
    float* Ob = g_att + ((size_t)b_ * T_ + (size_t)qi * 64) * (H_ * D_) + h * D_;
#pragma unroll
    for (int mi = 0; mi < 2; mi++) {
        float li0 = 1.f / sL[m0 + 16 * mi + lr];
        float li1 = 1.f / sL[m0 + 16 * mi + 8 + lr];
#pragma unroll
        for (int ni = 0; ni < 2; ni++)
#pragma unroll
            for (int rr = 0; rr < 4; rr++) {
                int r = m0 + 16 * mi + lr + (rr >= 2 ? 8 : 0);
                int c = n0 + 8 * ni + lc * 2 + (rr & 1);
                float li = (rr >= 2) ? li1 : li0;
                Ob[(size_t)r * (H_ * D_) + c] = o[mi][ni][rr] * li;
            }
    }
}

// ---------------------------------------------------------------------------
// Kernel 3: output projection + bias. C[8192,1024] = att @ Wproj + bproj.
// Same tiling as kernel 1. Grid (64, 16).
// ---------------------------------------------------------------------------
__global__ __launch_bounds__(256) void proj_mma_kernel(
    const float* __restrict__ Wp,
    const float* __restrict__ bias,
    float* __restrict__ C) {
    __shared__ uint32_t sA[128 * 36];
    __shared__ uint32_t sB[32 * 72];

    const int mt = blockIdx.x;   // 0..63
    const int nt = blockIdx.y;   // 0..15
    const int tid = threadIdx.x;
    const int w = tid >> 5, lane = tid & 31;
    const int wm = w >> 1, wn = w & 1;
    const int m0 = wm * 32, n0 = wn * 32;
    const int lr = lane >> 2, lc = lane & 3;

    const float* Ab = g_att + (size_t)mt * 128 * E_;
    const float* Bw = Wp + (size_t)nt * 64;

    float acc[2][4][4];
#pragma unroll
    for (int mi = 0; mi < 2; mi++)
#pragma unroll
        for (int ni = 0; ni < 4; ni++)
#pragma unroll
            for (int rr = 0; rr < 4; rr++) acc[mi][ni][rr] = 0.f;

    for (int k0 = 0; k0 < E_; k0 += 32) {
#pragma unroll
        for (int l = 0; l < 4; l++) {
            int idx = tid + l * 256;
            int r = idx >> 3, c4 = (idx & 7) * 4;
            float4 v = *reinterpret_cast<const float4*>(Ab + (size_t)r * E_ + k0 + c4);
            sA[r * 36 + c4 + 0] = f2tf(v.x);
            sA[r * 36 + c4 + 1] = f2tf(v.y);
            sA[r * 36 + c4 + 2] = f2tf(v.z);
            sA[r * 36 + c4 + 3] = f2tf(v.w);
        }
#pragma unroll
        for (int l = 0; l < 2; l++) {
            int idx = tid + l * 256;
            int r = idx >> 4, c4 = (idx & 15) * 4;
            float4 v = *reinterpret_cast<const float4*>(Bw + (size_t)(k0 + r) * E_ + c4);
            sB[r * 72 + c4 + 0] = f2tf(v.x);
            sB[r * 72 + c4 + 1] = f2tf(v.y);
            sB[r * 72 + c4 + 2] = f2tf(v.z);
            sB[r * 72 + c4 + 3] = f2tf(v.w);
        }
        __syncthreads();

#pragma unroll
        for (int ks = 0; ks < 32; ks += 8) {
            uint32_t a[2][4], b[4][2];
#pragma unroll
            for (int mi = 0; mi < 2; mi++) {
                int r0 = m0 + 16 * mi + lr;
                a[mi][0] = sA[r0 * 36 + ks + lc];
                a[mi][1] = sA[(r0 + 8) * 36 + ks + lc];
                a[mi][2] = sA[r0 * 36 + ks + 4 + lc];
                a[mi][3] = sA[(r0 + 8) * 36 + ks + 4 + lc];
            }
#pragma unroll
            for (int ni = 0; ni < 4; ni++) {
                int cb = n0 + 8 * ni + lr;
                b[ni][0] = sB[(ks + lc) * 72 + cb];
                b[ni][1] = sB[(ks + 4 + lc) * 72 + cb];
            }
#pragma unroll
            for (int mi = 0; mi < 2; mi++)
#pragma unroll
                for (int ni = 0; ni < 4; ni++) mma_tf32(acc[mi][ni], a[mi], b[ni]);
        }
        __syncthreads();
    }

    float* Cb = C + (size_t)mt * 128 * E_ + (size_t)nt * 64;
#pragma unroll
    for (int mi = 0; mi < 2; mi++)
#pragma unroll
        for (int ni = 0; ni < 4; ni++)
#pragma unroll
            for (int rr = 0; rr < 4; rr++) {
                int row = m0 + 16 * mi + lr + (rr >= 2 ? 8 : 0);
                int col = n0 + 8 * ni + lc * 2 + (rr & 1);
                Cb[(size_t)row * E_ + col] = acc[mi][ni][rr] + bias[nt * 64 + col];
            }
}

// ---------------------------------------------------------------------------
extern "C" void kernel_launch(void* const* d_in, const int* in_sizes, int n_in,
                              void* d_out, int out_size) {
    const float* x     = (const float*)d_in[0];
    const float* Wq    = (const float*)d_in[1];
    const float* Wk    = (const float*)d_in[2];
    const float* Wv    = (const float*)d_in[3];
    const float* Wproj = (const float*)d_in[4];
    const float* bproj = (const float*)d_in[5];
    float* out = (float*)d_out;

    // QKV: 64 M-tiles x 48 (which,h) tiles
    qkv_mma_kernel<<<dim3(64, 48), 256>>>(x, Wq, Wk, Wv);

    // attention: 32 q-tiles x 64 (b,h)
    const int attn_smem = (64 * 68 * 3 + 64 * 72 + 3 * 64) * (int)sizeof(uint32_t);
    cudaFuncSetAttribute(attn_mma_kernel, cudaFuncAttributeMaxDynamicSharedMemorySize, attn_smem);
    attn_mma_kernel<<<dim3(32, 64), 256, attn_smem>>>();

    // output projection: 64 M-tiles x 16 N-tiles
    proj_mma_kernel<<<dim3(64, 16), 256>>>(Wproj, bproj, out);
}

// round 4
// speedup vs baseline: 3.2430x; 1.1602x over previous
#include <cuda_runtime.h>
#include <cstdint>
#include <cstddef>

#define B_ 4
#define T_ 2048
#define E_ 1024
#define H_ 16
#define D_ 64

// Scratch. q,k,v: [B*H][T][D], values pre-rounded to tf32. att: [B,T,H*D] pre-rounded.
__device__ float g_q[(size_t)B_ * H_ * T_ * D_];
__device__ float g_k[(size_t)B_ * H_ * T_ * D_];
__device__ float g_v[(size_t)B_ * H_ * T_ * D_];
__device__ float g_att[(size_t)B_ * T_ * H_ * D_];

__device__ __forceinline__ uint32_t f2tf(float f) {
    uint32_t r;
    asm("cvt.rna.tf32.f32 %0, %1;" : "=r"(r) : "f"(f));
    return r;
}

__device__ __forceinline__ void mma_tf32(float c[4], const uint32_t a[4], const uint32_t b[2]) {
    asm volatile(
        "mma.sync.aligned.m16n8k8.row.col.f32.tf32.tf32.f32 "
        "{%0,%1,%2,%3}, {%4,%5,%6,%7}, {%8,%9}, {%0,%1,%2,%3};"
        : "+f"(c[0]), "+f"(c[1]), "+f"(c[2]), "+f"(c[3])
        : "r"(a[0]), "r"(a[1]), "r"(a[2]), "r"(a[3]), "r"(b[0]), "r"(b[1]));
}

// ---------------------------------------------------------------------------
// Kernel 1: fused QKV GEMM. C[8192,3072] = X @ Wcat. BM=128,BN=128,BK=32.
// 8 warps 2(M)x4(N), warp tile 64x32 (mi=4, ni=4). Reg-staged prefetch.
// ---------------------------------------------------------------------------
__global__ __launch_bounds__(256) void qkv_mma_kernel(
    const float* __restrict__ x,
    const float* __restrict__ Wq,
    const float* __restrict__ Wk,
    const float* __restrict__ Wv) {
    __shared__ uint32_t sA[128 * 36];
    __shared__ uint32_t sB[32 * 136];

    const int mt = blockIdx.x;          // 0..63
    const int nt = blockIdx.y;          // 0..23
    const int ncol0 = nt * 128;
    const int which = ncol0 >> 10;
    const int h0 = (ncol0 & 1023) >> 6;
    const float* W = (which == 0 ? Wq : (which == 1 ? Wk : Wv));
    const float* Wh0 = W + (size_t)h0 * E_ * D_;

    const int tid = threadIdx.x;
    const int w = tid >> 5, lane = tid & 31;
    const int wm = w >> 2, wn = w & 3;
    const int m0 = wm * 64, n0 = wn * 32;
    const int lr = lane >> 2, lc = lane & 3;

    const float* Xb = x + (size_t)mt * 128 * E_;

    float acc[4][4][4] = {};
    float4 pa[4], pb[4];

    // prefetch stage 0
#pragma unroll
    for (int l = 0; l < 4; l++) {
        int idx = tid + l * 256;
        { int r = idx >> 3, f = idx & 7;
          pa[l] = *reinterpret_cast<const float4*>(Xb + (size_t)r * E_ + 4 * f); }
        { int r = idx >> 5, c = (idx & 31) * 4;
          pb[l] = *reinterpret_cast<const float4*>(
              Wh0 + (size_t)(c >> 6) * E_ * D_ + (size_t)r * D_ + (c & 63)); }
    }

    for (int k0 = 0; k0 < E_; k0 += 32) {
#pragma unroll
        for (int l = 0; l < 4; l++) {
            int idx = tid + l * 256;
            { int r = idx >> 3, f = idx & 7;
              uint4 u = { f2tf(pa[l].x), f2tf(pa[l].y), f2tf(pa[l].z), f2tf(pa[l].w) };
              *reinterpret_cast<uint4*>(&sA[r * 36 + 4 * f]) = u; }
            { int r = idx >> 5, f = idx & 31;
              uint4 u = { f2tf(pb[l].x), f2tf(pb[l].y), f2tf(pb[l].z), f2tf(pb[l].w) };
              *reinterpret_cast<uint4*>(&sB[r * 136 + 4 * f]) = u; }
        }
        __syncthreads();
        if (k0 + 32 < E_) {
#pragma unroll
            for (int l = 0; l < 4; l++) {
                int idx = tid + l * 256;
                { int r = idx >> 3, f = idx & 7;
                  pa[l] = *reinterpret_cast<const float4*>(Xb + (size_t)r * E_ + k0 + 32 + 4 * f); }
                { int r = idx >> 5, c = (idx & 31) * 4;
                  pb[l] = *reinterpret_cast<const float4*>(
                      Wh0 + (size_t)(c >> 6) * E_ * D_ + (size_t)(k0 + 32 + r) * D_ + (c & 63)); }
            }
        }
#pragma unroll
        for (int ks = 0; ks < 32; ks += 8) {
            uint32_t a[4][4], b[4][2];
#pragma unroll
            for (int mi = 0; mi < 4; mi++) {
                int r0 = m0 + 16 * mi + lr;
                a[mi][0] = sA[r0 * 36 + ks + lc];
                a[mi][1] = sA[(r0 + 8) * 36 + ks + lc];
                a[mi][2] = sA[r0 * 36 + ks + 4 + lc];
                a[mi][3] = sA[(r0 + 8) * 36 + ks + 4 + lc];
            }
#pragma unroll
            for (int ni = 0; ni < 4; ni++) {
                int cb = n0 + 8 * ni + lr;
                b[ni][0] = sB[(ks + lc) * 136 + cb];
                b[ni][1] = sB[(ks + 4 + lc) * 136 + cb];
            }
#pragma unroll
            for (int mi = 0; mi < 4; mi++)
#pragma unroll
                for (int ni = 0; ni < 4; ni++) mma_tf32(acc[mi][ni], a[mi], b[ni]);
        }
        __syncthreads();
    }

    float* outsel = (which == 0 ? g_q : (which == 1 ? g_k : g_v));
    const int b_ = (mt * 128) / T_;
    const int trow0 = (mt * 128) % T_;
#pragma unroll
    for (int mi = 0; mi < 4; mi++)
#pragma unroll
        for (int ni = 0; ni < 4; ni++) {
            int col = n0 + 8 * ni + 2 * lc;
            int hh = h0 + (col >> 6), dd = col & 63;
            float* base = outsel + ((size_t)(b_ * H_ + hh) * T_ + trow0) * D_ + dd;
            int row0 = m0 + 16 * mi + lr;
            float2 v0 = { __uint_as_float(f2tf(acc[mi][ni][0])),
                          __uint_as_float(f2tf(acc[mi][ni][1])) };
            float2 v1 = { __uint_as_float(f2tf(acc[mi][ni][2])),
                          __uint_as_float(f2tf(acc[mi][ni][3])) };
            *reinterpret_cast<float2*>(base + (size_t)row0 * D_) = v0;
            *reinterpret_cast<float2*>(base + (size_t)(row0 + 8) * D_) = v1;
        }
}

// ---------------------------------------------------------------------------
// Kernel 2: causal flash attention. Q-tile 128 x kv-tile 64. 8 warps, each warp
// 16 q-rows x 64 kv. Q frags in regs; softmax in regs (quad shuffles);
// P transposed to A-frags via shuffles. K/V reg-staged prefetch, single buffer.
// ---------------------------------------------------------------------------
__global__ __launch_bounds__(256) void attn_mma_kernel() {
    __shared__ uint32_t sK[64 * 68];
    __shared__ uint32_t sV[64 * 72];

    const int qi = (int)gridDim.x - 1 - (int)blockIdx.x;  // 15..0, biggest first
    const int bh = blockIdx.y;
    const int tid = threadIdx.x;
    const int w = tid >> 5, lane = tid & 31;
    const int lr = lane >> 2, lc = lane & 3;
    const int r_warp = w * 16;
    const float sc2 = 0.125f * 1.44269504f;  // scale * log2(e)

    const float* Qb = g_q + ((size_t)bh * T_ + (size_t)qi * 128) * D_;
    const float* Kb = g_k + (size_t)bh * T_ * D_;
    const float* Vb = g_v + (size_t)bh * T_ * D_;

    // Q fragments straight from gmem (pre-rounded tf32 bits)
    uint32_t qa[8][4];
#pragma unroll
    for (int kk = 0; kk < 8; kk++) {
        const float* q0 = Qb + (size_t)(r_warp + lr) * D_ + 8 * kk;
        const float* q1 = Qb + (size_t)(r_warp + lr + 8) * D_ + 8 * kk;
        qa[kk][0] = __float_as_uint(q0[lc]);
        qa[kk][1] = __float_as_uint(q1[lc]);
        qa[kk][2] = __float_as_uint(q0[lc + 4]);
        qa[kk][3] = __float_as_uint(q1[lc + 4]);
    }

    float m0r = -1e30f, m1r = -1e30f, l0 = 0.f, l1 = 0.f;
    float o[8][4] = {};

    const int jmax = 2 * qi + 1;
    float4 pk[4], pv[4];
#pragma unroll
    for (int l = 0; l < 4; l++) {
        int idx = tid + l * 256;
        int r = idx >> 4, f = idx & 15;
        pk[l] = *reinterpret_cast<const float4*>(Kb + (size_t)r * D_ + 4 * f);
        pv[l] = *reinterpret_cast<const float4*>(Vb + (size_t)r * D_ + 4 * f);
    }

    for (int j = 0; j <= jmax; j++) {
        __syncthreads();
#pragma unroll
        for (int l = 0; l < 4; l++) {
            int idx = tid + l * 256;
            int r = idx >> 4, f = idx & 15;
            *reinterpret_cast<float4*>(&sK[r * 68 + 4 * f]) = pk[l];
            *reinterpret_cast<float4*>(&sV[r * 72 + 4 * f]) = pv[l];
        }
        __syncthreads();
        if (j < jmax) {
            const float* Kj = Kb + (size_t)(j + 1) * 64 * D_;
            const float* Vj = Vb + (size_t)(j + 1) * 64 * D_;
#pragma unroll
            for (int l = 0; l < 4; l++) {
                int idx = tid + l * 256;
                int r = idx >> 4, f = idx & 15;
                pk[l] = *reinterpret_cast<const float4*>(Kj + (size_t)r * D_ + 4 * f);
                pv[l] = *reinterpret_cast<const float4*>(Vj + (size_t)r * D_ + 4 * f);
            }
        }

        // S = Q K^T : 16 x 64 per warp
        float s[8][4] = {};
#pragma unroll
        for (int kk = 0; kk < 8; kk++) {
#pragma unroll
            for (int ni = 0; ni < 8; ni++) {
                uint32_t b[2];
                int kr = 8 * ni + lr;
                b[0] = sK[kr * 68 + 8 * kk + lc];
                b[1] = sK[kr * 68 + 8 * kk + 4 + lc];
                mma_tf32(s[ni], qa[kk], b);
            }
        }

        // scale to base-2 + causal mask
        const int rg0 = qi * 128 + r_warp + lr;
        const int rg1 = rg0 + 8;
        if (j * 64 + 63 > qi * 128 + r_warp) {
#pragma unroll
            for (int ni = 0; ni < 8; ni++) {
                int c0 = j * 64 + 8 * ni + 2 * lc;
                s[ni][0] = (c0 <= rg0) ? s[ni][0] * sc2 : -1e30f;
                s[ni][1] = (c0 + 1 <= rg0) ? s[ni][1] * sc2 : -1e30f;
                s[ni][2] = (c0 <= rg1) ? s[ni][2] * sc2 : -1e30f;
                s[ni][3] = (c0 + 1 <= rg1) ? s[ni][3] * sc2 : -1e30f;
            }
        } else {
#pragma unroll
            for (int ni = 0; ni < 8; ni++) {
                s[ni][0] *= sc2; s[ni][1] *= sc2; s[ni][2] *= sc2; s[ni][3] *= sc2;
            }
        }

        // register softmax (rows lr and lr+8; quad reduce)
        float mx0 = -1e30f, mx1 = -1e30f;
#pragma unroll
        for (int ni = 0; ni < 8; ni++) {
            mx0 = fmaxf(mx0, fmaxf(s[ni][0], s[ni][1]));
            mx1 = fmaxf(mx1, fmaxf(s[ni][2], s[ni][3]));
        }
        mx0 = fmaxf(mx0, __shfl_xor_sync(0xffffffffu, mx0, 1));
        mx0 = fmaxf(mx0, __shfl_xor_sync(0xffffffffu, mx0, 2));
        mx1 = fmaxf(mx1, __shfl_xor_sync(0xffffffffu, mx1, 1));
        mx1 = fmaxf(mx1, __shfl_xor_sync(0xffffffffu, mx1, 2));
        float mn0 = fmaxf(m0r, mx0), mn1 = fmaxf(m1r, mx1);
        float al0 = exp2f(m0r - mn0), al1 = exp2f(m1r - mn1);
        m0r = mn0; m1r = mn1;
        float ps0 = 0.f, ps1 = 0.f;
#pragma unroll
        for (int ni = 0; ni < 8; ni++) {
            float p0 = __uint_as_float(f2tf(exp2f(s[ni][0] - mn0)));
            float p1 = __uint_as_float(f2tf(exp2f(s[ni][1] - mn0)));
            float p2 = __uint_as_float(f2tf(exp2f(s[ni][2] - mn1)));
            float p3 = __uint_as_float(f2tf(exp2f(s[ni][3] - mn1)));
            s[ni][0] = p0; s[ni][1] = p1; s[ni][2] = p2; s[ni][3] = p3;
            ps0 += p0 + p1; ps1 += p2 + p3;
        }
        ps0 += __shfl_xor_sync(0xffffffffu, ps0, 1);
        ps0 += __shfl_xor_sync(0xffffffffu, ps0, 2);
        ps1 += __shfl_xor_sync(0xffffffffu, ps1, 1);
        ps1 += __shfl_xor_sync(0xffffffffu, ps1, 2);
        l0 = l0 * al0 + ps0;
        l1 = l1 * al1 + ps1;

#pragma unroll
        for (int ni = 0; ni < 8; ni++) {
            o[ni][0] *= al0; o[ni][1] *= al0; o[ni][2] *= al1; o[ni][3] *= al1;
        }

        // P @ V : transpose P (C-layout) -> A-frags via quad shuffles
        const int srcA = (lane & ~3) | (lc >> 1);
        const int srcB = srcA + 2;
#pragma unroll
        for (int kk = 0; kk < 8; kk++) {
            float v0a = __shfl_sync(0xffffffffu, s[kk][0], srcA);
            float v1a = __shfl_sync(0xffffffffu, s[kk][1], srcA);
            float v2a = __shfl_sync(0xffffffffu, s[kk][2], srcA);
            float v3a = __shfl_sync(0xffffffffu, s[kk][3], srcA);
            float v0b = __shfl_sync(0xffffffffu, s[kk][0], srcB);
            float v1b = __shfl_sync(0xffffffffu, s[kk][1], srcB);
            float v2b = __shfl_sync(0xffffffffu, s[kk][2], srcB);
            float v3b = __shfl_sync(0xffffffffu, s[kk][3], srcB);
            uint32_t a[4];
            a[0] = __float_as_uint((lc & 1) ? v1a : v0a);
            a[1] = __float_as_uint((lc & 1) ? v3a : v2a);
            a[2] = __float_as_uint((lc & 1) ? v1b : v0b);
            a[3] = __float_as_uint((lc & 1) ? v3b : v2b);
#pragma unroll
            for (int ni = 0; ni < 8; ni++) {
                uint32_t b[2];
                b[0] = sV[(8 * kk + lc) * 72 + 8 * ni + lr];
                b[1] = sV[(8 * kk + 4 + lc) * 72 + 8 * ni + lr];
                mma_tf32(o[ni], a, b);
            }
        }
    }

    // epilogue: att layout [B, T, H*D], pre-rounded to tf32
    const float il0 = 1.f / l0, il1 = 1.f / l1;
    const int b_ = bh >> 4, h = bh & 15;
    float* Ob = g_att + ((size_t)b_ * T_ + (size_t)qi * 128 + r_warp) * (H_ * D_) + h * D_;
#pragma unroll
    for (int ni = 0; ni < 8; ni++) {
        int c = 8 * ni + 2 * lc;
        float2 v0 = { __uint_as_float(f2tf(o[ni][0] * il0)),
                      __uint_as_float(f2tf(o[ni][1] * il0)) };
        float2 v1 = { __uint_as_float(f2tf(o[ni][2] * il1)),
                      __uint_as_float(f2tf(o[ni][3] * il1)) };
        *reinterpret_cast<float2*>(&Ob[(size_t)lr * (H_ * D_) + c]) = v0;
        *reinterpret_cast<float2*>(&Ob[(size_t)(lr + 8) * (H_ * D_) + c]) = v1;
    }
}

// ---------------------------------------------------------------------------
// Kernel 3: output projection + bias. Same tiling as kernel 1.
// ---------------------------------------------------------------------------
__global__ __launch_bounds__(256) void proj_mma_kernel(
    const float* __restrict__ Wp,
    const float* __restrict__ bias,
    float* __restrict__ C) {
    __shared__ uint32_t sA[128 * 36];
    __shared__ uint32_t sB[32 * 136];

    const int mt = blockIdx.x;   // 0..63
    const int nt = blockIdx.y;   // 0..7
    const int tid = threadIdx.x;
    const int w = tid >> 5, lane = tid & 31;
    const int wm = w >> 2, wn = w & 3;
    const int m0 = wm * 64, n0 = wn * 32;
    const int lr = lane >> 2, lc = lane & 3;

    const float* Ab = g_att + (size_t)mt * 128 * E_;
    const float* Bw = Wp + (size_t)nt * 128;

    float acc[4][4][4] = {};
    float4 pa[4], pb[4];

#pragma unroll
    for (int l = 0; l < 4; l++) {
        int idx = tid + l * 256;
        { int r = idx >> 3, f = idx & 7;
          pa[l] = *reinterpret_cast<const float4*>(Ab + (size_t)r * E_ + 4 * f); }
        { int r = idx >> 5, f = idx & 31;
          pb[l] = *reinterpret_cast<const float4*>(Bw + (size_t)r * E_ + 4 * f); }
    }

    for (int k0 = 0; k0 < E_; k0 += 32) {
#pragma unroll
        for (int l = 0; l < 4; l++) {
            int idx = tid + l * 256;
            { int r = idx >> 3, f = idx & 7;
              uint4 u = { f2tf(pa[l].x), f2tf(pa[l].y), f2tf(pa[l].z), f2tf(pa[l].w) };
              *reinterpret_cast<uint4*>(&sA[r * 36 + 4 * f]) = u; }
            { int r = idx >> 5, f = idx & 31;
              uint4 u = { f2tf(pb[l].x), f2tf(pb[l].y), f2tf(pb[l].z), f2tf(pb[l].w) };
              *reinterpret_cast<uint4*>(&sB[r * 136 + 4 * f]) = u; }
        }
        __syncthreads();
        if (k0 + 32 < E_) {
#pragma unroll
            for (int l = 0; l < 4; l++) {
                int idx = tid + l * 256;
                { int r = idx >> 3, f = idx & 7;
                  pa[l] = *reinterpret_cast<const float4*>(Ab + (size_t)r * E_ + k0 + 32 + 4 * f); }
                { int r = idx >> 5, f = idx & 31;
                  pb[l] = *reinterpret_cast<const float4*>(Bw + (size_t)(k0 + 32 + r) * E_ + 4 * f); }
            }
        }
#pragma unroll
        for (int ks = 0; ks < 32; ks += 8) {
            uint32_t a[4][4], b[4][2];
#pragma unroll
            for (int mi = 0; mi < 4; mi++) {
                int r0 = m0 + 16 * mi + lr;
                a[mi][0] = sA[r0 * 36 + ks + lc];
                a[mi][1] = sA[(r0 + 8) * 36 + ks + lc];
                a[mi][2] = sA[r0 * 36 + ks + 4 + lc];
                a[mi][3] = sA[(r0 + 8) * 36 + ks + 4 + lc];
            }
#pragma unroll
            for (int ni = 0; ni < 4; ni++) {
                int cb = n0 + 8 * ni + lr;
                b[ni][0] = sB[(ks + lc) * 136 + cb];
                b[ni][1] = sB[(ks + 4 + lc) * 136 + cb];
            }
#pragma unroll
            for (int mi = 0; mi < 4; mi++)
#pragma unroll
                for (int ni = 0; ni < 4; ni++) mma_tf32(acc[mi][ni], a[mi], b[ni]);
        }
        __syncthreads();
    }

    float* Cb = C + (size_t)mt * 128 * E_ + (size_t)nt * 128;
#pragma unroll
    for (int mi = 0; mi < 4; mi++)
#pragma unroll
        for (int ni = 0; ni < 4; ni++) {
            int col = n0 + 8 * ni + 2 * lc;
            float b0 = bias[nt * 128 + col], b1 = bias[nt * 128 + col + 1];
            int row0 = m0 + 16 * mi + lr;
            float2 v0 = { acc[mi][ni][0] + b0, acc[mi][ni][1] + b1 };
            float2 v1 = { acc[mi][ni][2] + b0, acc[mi][ni][3] + b1 };
            *reinterpret_cast<float2*>(Cb + (size_t)row0 * E_ + col) = v0;
            *reinterpret_cast<float2*>(Cb + (size_t)(row0 + 8) * E_ + col) = v1;
        }
}

// ---------------------------------------------------------------------------
extern "C" void kernel_launch(void* const* d_in, const int* in_sizes, int n_in,
                              void* d_out, int out_size) {
    const float* x     = (const float*)d_in[0];
    const float* Wq    = (const float*)d_in[1];
    const float* Wk    = (const float*)d_in[2];
    const float* Wv    = (const float*)d_in[3];
    const float* Wproj = (const float*)d_in[4];
    const float* bproj = (const float*)d_in[5];
    float* out = (float*)d_out;

    qkv_mma_kernel<<<dim3(64, 24), 256>>>(x, Wq, Wk, Wv);
    attn_mma_kernel<<<dim3(16, 64), 256>>>();
    proj_mma_kernel<<<dim3(64, 8), 256>>>(Wproj, bproj, out);
}

// round 6
// speedup vs baseline: 3.7124x; 1.1448x over previous
#include <cuda_runtime.h>
#include <cstdint>
#include <cstddef>

#define B_ 4
#define T_ 2048
#define E_ 1024
#define H_ 16
#define D_ 64

// Scratch. q,k,v: [B*H][T][D] tf32-rounded. att: [B,T,H*D] tf32-rounded.
// g_x/g_w/g_wp: tf32-rounded copies of inputs.
__device__ float g_q[(size_t)B_ * H_ * T_ * D_];
__device__ float g_k[(size_t)B_ * H_ * T_ * D_];
__device__ float g_v[(size_t)B_ * H_ * T_ * D_];
__device__ float g_att[(size_t)B_ * T_ * H_ * D_];
__device__ float g_x[(size_t)B_ * T_ * E_];
__device__ float g_w[(size_t)3 * H_ * E_ * D_];
__device__ float g_wp[(size_t)E_ * E_];

__device__ __forceinline__ uint32_t f2tf(float f) {
    uint32_t r;
    asm("cvt.rna.tf32.f32 %0, %1;" : "=r"(r) : "f"(f));
    return r;
}

__device__ __forceinline__ void mma_tf32(float c[4], const uint32_t a[4], const uint32_t b[2]) {
    asm volatile(
        "mma.sync.aligned.m16n8k8.row.col.f32.tf32.tf32.f32 "
        "{%0,%1,%2,%3}, {%4,%5,%6,%7}, {%8,%9}, {%0,%1,%2,%3};"
        : "+f"(c[0]), "+f"(c[1]), "+f"(c[2]), "+f"(c[3])
        : "r"(a[0]), "r"(a[1]), "r"(a[2]), "r"(a[3]), "r"(b[0]), "r"(b[1]));
}

__device__ __forceinline__ uint32_t smem_u32(const void* p) {
    return (uint32_t)__cvta_generic_to_shared(p);
}
__device__ __forceinline__ void cp16(uint32_t s, const void* g) {
    asm volatile("cp.async.cg.shared.global [%0], [%1], 16;" :: "r"(s), "l"(g));
}
__device__ __forceinline__ void cp_commit() { asm volatile("cp.async.commit_group;"); }
__device__ __forceinline__ void cp_wait1() { asm volatile("cp.async.wait_group 1;"); }

// ---------------------------------------------------------------------------
// Kernel 0: pre-round a tensor to tf32 (float4, exact size).
// ---------------------------------------------------------------------------
__global__ __launch_bounds__(256) void prep_kernel(
    const float4* __restrict__ src, float4* __restrict__ dst, int n4) {
    int i = blockIdx.x * 256 + threadIdx.x;
    if (i < n4) {
        float4 v = src[i];
        float4 o;
        o.x = __uint_as_float(f2tf(v.x));
        o.y = __uint_as_float(f2tf(v.y));
        o.z = __uint_as_float(f2tf(v.z));
        o.w = __uint_as_float(f2tf(v.w));
        dst[i] = o;
    }
}

// ---------------------------------------------------------------------------
// Kernel 1: fused QKV GEMM from pre-rounded g_x/g_w. BM=128,BN=128,BK=32.
// 8 warps 2(M)x4(N), warp tile 64x32. cp.async 2-stage smem pipeline.
// Stage layout (words): sA 128*36 = 4608, sB 32*136 = 4352; stage = 8960.
// ---------------------------------------------------------------------------
#define GEMM_STAGE_W 8960

__global__ __launch_bounds__(256, 2) void qkv_mma_kernel() {
    extern __shared__ uint32_t dyn[];

    const int mt = blockIdx.x;          // 0..63
    const int nt = blockIdx.y;          // 0..23
    const int ncol0 = nt * 128;
    const int which = ncol0 >> 10;
    const int h0 = (ncol0 & 1023) >> 6;
    const float* gw = g_w + (size_t)which * H_ * E_ * D_ + (size_t)h0 * E_ * D_;
    const float* gx = g_x + (size_t)mt * 128 * E_;

    const int tid = threadIdx.x;
    const int w = tid >> 5, lane = tid & 31;
    const int wm = w >> 2, wn = w & 3;
    const int m0 = wm * 64, n0 = wn * 32;
    const int lr = lane >> 2, lc = lane & 3;

    float acc[4][4][4] = {};

#define QKV_ISSUE(stg, k0)                                                        \
    {                                                                             \
        uint32_t* sA_ = dyn + (stg) * GEMM_STAGE_W;                               \
        uint32_t* sB_ = sA_ + 4608;                                               \
        _Pragma("unroll")                                                         \
        for (int l = 0; l < 4; l++) {                                             \
            int idx = tid + l * 256;                                              \
            { int r = idx >> 3, f = (idx & 7) * 4;                                \
              cp16(smem_u32(&sA_[r * 36 + f]), gx + (size_t)r * E_ + (k0) + f); } \
            { int r = idx >> 5, c = (idx & 31) * 4;                               \
              cp16(smem_u32(&sB_[r * 136 + c]),                                   \
                   gw + (size_t)(c >> 6) * E_ * D_ + (size_t)((k0) + r) * D_ + (c & 63)); } \
        }                                                                         \
    }

    QKV_ISSUE(0, 0); cp_commit();
    QKV_ISSUE(1, 32); cp_commit();

    for (int it = 0; it < 32; it++) {
        cp_wait1();
        __syncthreads();
        const uint32_t* sA = dyn + (it & 1) * GEMM_STAGE_W;
        const uint32_t* sB = sA + 4608;
#pragma unroll
        for (int ks = 0; ks < 32; ks += 8) {
            uint32_t a[4][4], b[4][2];
#pragma unroll
            for (int mi = 0; mi < 4; mi++) {
                int r0 = m0 + 16 * mi + lr;
                a[mi][0] = sA[r0 * 36 + ks + lc];
                a[mi][1] = sA[(r0 + 8) * 36 + ks + lc];
                a[mi][2] = sA[r0 * 36 + ks + 4 + lc];
                a[mi][3] = sA[(r0 + 8) * 36 + ks + 4 + lc];
            }
#pragma unroll
            for (int ni = 0; ni < 4; ni++) {
                int cb = n0 + 8 * ni + lr;
                b[ni][0] = sB[(ks + lc) * 136 + cb];
                b[ni][1] = sB[(ks + 4 + lc) * 136 + cb];
            }
#pragma unroll
            for (int mi = 0; mi < 4; mi++)
#pragma unroll
                for (int ni = 0; ni < 4; ni++) mma_tf32(acc[mi][ni], a[mi], b[ni]);
        }
        __syncthreads();
        if (it + 2 < 32) QKV_ISSUE(it & 1, (it + 2) * 32);
        cp_commit();
    }

    float* outsel = (which == 0 ? g_q : (which == 1 ? g_k : g_v));
    const int b_ = (mt * 128) / T_;
    const int trow0 = (mt * 128) % T_;
#pragma unroll
    for (int mi = 0; mi < 4; mi++)
#pragma unroll
        for (int ni = 0; ni < 4; ni++) {
            int col = n0 + 8 * ni + 2 * lc;
            int hh = h0 + (col >> 6), dd = col & 63;
            float* base = outsel + ((size_t)(b_ * H_ + hh) * T_ + trow0) * D_ + dd;
            int row0 = m0 + 16 * mi + lr;
            float2 v0 = { __uint_as_float(f2tf(acc[mi][ni][0])),
                          __uint_as_float(f2tf(acc[mi][ni][1])) };
            float2 v1 = { __uint_as_float(f2tf(acc[mi][ni][2])),
                          __uint_as_float(f2tf(acc[mi][ni][3])) };
            *reinterpret_cast<float2*>(base + (size_t)row0 * D_) = v0;
            *reinterpret_cast<float2*>(base + (size_t)(row0 + 8) * D_) = v1;
        }
}

// ---------------------------------------------------------------------------
// Kernel 2: causal flash attention. Q-tile 128 x kv-tile 64, 8 warps, each
// warp 16 q-rows x 64 kv. Q frags in regs; softmax in regs; P transposed via
// quad shuffles. K/V via cp.async 2-stage pipeline.
// Stage layout (words): sK 64*68 = 4352, sV 64*72 = 4608; stage = 8960.
// ---------------------------------------------------------------------------
__global__ __launch_bounds__(256, 2) void attn_mma_kernel() {
    extern __shared__ uint32_t dyn[];

    const int qi = (int)gridDim.x - 1 - (int)blockIdx.x;  // 15..0, biggest first
    const int bh = blockIdx.y;
    const int tid = threadIdx.x;
    const int w = tid >> 5, lane = tid & 31;
    const int lr = lane >> 2, lc = lane & 3;
    const int r_warp = w * 16;
    const float sc2 = 0.125f * 1.44269504f;  // scale * log2(e)

    const float* Qb = g_q + ((size_t)bh * T_ + (size_t)qi * 128) * D_;
    const float* Kb = g_k + (size_t)bh * T_ * D_;
    const float* Vb = g_v + (size_t)bh * T_ * D_;

#define ATTN_ISSUE(stg, jt)                                                     \
    {                                                                           \
        uint32_t* sK_ = dyn + (stg) * GEMM_STAGE_W;                             \
        uint32_t* sV_ = sK_ + 4352;                                             \
        const float* Kj_ = Kb + (size_t)(jt) * 64 * D_;                         \
        const float* Vj_ = Vb + (size_t)(jt) * 64 * D_;                         \
        _Pragma("unroll")                                                       \
        for (int l = 0; l < 4; l++) {                                           \
            int idx = tid + l * 256;                                            \
            int r = idx >> 4, f = (idx & 15) * 4;                               \
            cp16(smem_u32(&sK_[r * 68 + f]), Kj_ + (size_t)r * D_ + f);         \
            cp16(smem_u32(&sV_[r * 72 + f]), Vj_ + (size_t)r * D_ + f);         \
        }                                                                       \
    }

    // Q fragments straight from gmem (pre-rounded tf32 bits)
    uint32_t qa[8][4];
#pragma unroll
    for (int kk = 0; kk < 8; kk++) {
        const float* q0 = Qb + (size_t)(r_warp + lr) * D_ + 8 * kk;
        const float* q1 = Qb + (size_t)(r_warp + lr + 8) * D_ + 8 * kk;
        qa[kk][0] = __float_as_uint(q0[lc]);
        qa[kk][1] = __float_as_uint(q1[lc]);
        qa[kk][2] = __float_as_uint(q0[lc + 4]);
        qa[kk][3] = __float_as_uint(q1[lc + 4]);
    }

    float m0r = -1e30f, m1r = -1e30f, l0 = 0.f, l1 = 0.f;
    float o[8][4] = {};

    const int jmax = 2 * qi + 1;   // >= 1 always
    ATTN_ISSUE(0, 0); cp_commit();
    ATTN_ISSUE(1, 1); cp_commit();

    for (int j = 0; j <= jmax; j++) {
        cp_wait1();
        __syncthreads();
        const uint32_t* sK = dyn + (j & 1) * GEMM_STAGE_W;
        const uint32_t* sV = sK + 4352;

        // S = Q K^T : 16 x 64 per warp
        float s[8][4] = {};
#pragma unroll
        for (int kk = 0; kk < 8; kk++) {
#pragma unroll
            for (int ni = 0; ni < 8; ni++) {
                uint32_t b[2];
                int kr = 8 * ni + lr;
                b[0] = sK[kr * 68 + 8 * kk + lc];
                b[1] = sK[kr * 68 + 8 * kk + 4 + lc];
                mma_tf32(s[ni], qa[kk], b);
            }
        }

        // scale to base-2 + causal mask
        const int rg0 = qi * 128 + r_warp + lr;
        const int rg1 = rg0 + 8;
        if (j * 64 + 63 > qi * 128 + r_warp) {
#pragma unroll
            for (int ni = 0; ni < 8; ni++) {
                int c0 = j * 64 + 8 * ni + 2 * lc;
                s[ni][0] = (c0 <= rg0) ? s[ni][0] * sc2 : -1e30f;
                s[ni][1] = (c0 + 1 <= rg0) ? s[ni][1] * sc2 : -1e30f;
                s[ni][2] = (c0 <= rg1) ? s[ni][2] * sc2 : -1e30f;
                s[ni][3] = (c0 + 1 <= rg1) ? s[ni][3] * sc2 : -1e30f;
            }
        } else {
#pragma unroll
            for (int ni = 0; ni < 8; ni++) {
                s[ni][0] *= sc2; s[ni][1] *= sc2; s[ni][2] *= sc2; s[ni][3] *= sc2;
            }
        }

        // register softmax (rows lr and lr+8; quad reduce)
        float mx0 = -1e30f, mx1 = -1e30f;
#pragma unroll
        for (int ni = 0; ni < 8; ni++) {
            mx0 = fmaxf(mx0, fmaxf(s[ni][0], s[ni][1]));
            mx1 = fmaxf(mx1, fmaxf(s[ni][2], s[ni][3]));
        }
        mx0 = fmaxf(mx0, __shfl_xor_sync(0xffffffffu, mx0, 1));
        mx0 = fmaxf(mx0, __shfl_xor_sync(0xffffffffu, mx0, 2));
        mx1 = fmaxf(mx1, __shfl_xor_sync(0xffffffffu, mx1, 1));
        mx1 = fmaxf(mx1, __shfl_xor_sync(0xffffffffu, mx1, 2));
        float mn0 = fmaxf(m0r, mx0), mn1 = fmaxf(m1r, mx1);
        float al0 = exp2f(m0r - mn0), al1 = exp2f(m1r - mn1);
        m0r = mn0; m1r = mn1;
        float ps0 = 0.f, ps1 = 0.f;
#pragma unroll
        for (int ni = 0; ni < 8; ni++) {
            float p0 = __uint_as_float(f2tf(exp2f(s[ni][0] - mn0)));
            float p1 = __uint_as_float(f2tf(exp2f(s[ni][1] - mn0)));
            float p2 = __uint_as_float(f2tf(exp2f(s[ni][2] - mn1)));
            float p3 = __uint_as_float(f2tf(exp2f(s[ni][3] - mn1)));
            s[ni][0] = p0; s[ni][1] = p1; s[ni][2] = p2; s[ni][3] = p3;
            ps0 += p0 + p1; ps1 += p2 + p3;
        }
        ps0 += __shfl_xor_sync(0xffffffffu, ps0, 1);
        ps0 += __shfl_xor_sync(0xffffffffu, ps0, 2);
        ps1 += __shfl_xor_sync(0xffffffffu, ps1, 1);
        ps1 += __shfl_xor_sync(0xffffffffu, ps1, 2);
        l0 = l0 * al0 + ps0;
        l1 = l1 * al1 + ps1;

#pragma unroll
        for (int ni = 0; ni < 8; ni++) {
            o[ni][0] *= al0; o[ni][1] *= al0; o[ni][2] *= al1; o[ni][3] *= al1;
        }

        // P @ V : transpose P (C-layout) -> A-frags via quad shuffles
        const int srcA = (lane & ~3) | (lc >> 1);
        const int srcB = srcA + 2;
#pragma unroll
        for (int kk = 0; kk < 8; kk++) {
            float v0a = __shfl_sync(0xffffffffu, s[kk][0], srcA);
            float v1a = __shfl_sync(0xffffffffu, s[kk][1], srcA);
            float v2a = __shfl_sync(0xffffffffu, s[kk][2], srcA);
            float v3a = __shfl_sync(0xffffffffu, s[kk][3], srcA);
            float v0b = __shfl_sync(0xffffffffu, s[kk][0], srcB);
            float v1b = __shfl_sync(0xffffffffu, s[kk][1], srcB);
            float v2b = __shfl_sync(0xffffffffu, s[kk][2], srcB);
            float v3b = __shfl_sync(0xffffffffu, s[kk][3], srcB);
            uint32_t a[4];
            a[0] = __float_as_uint((lc & 1) ? v1a : v0a);
            a[1] = __float_as_uint((lc & 1) ? v3a : v2a);
            a[2] = __float_as_uint((lc & 1) ? v1b : v0b);
            a[3] = __float_as_uint((lc & 1) ? v3b : v2b);
#pragma unroll
            for (int ni = 0; ni < 8; ni++) {
                uint32_t b[2];
                b[0] = sV[(8 * kk + lc) * 72 + 8 * ni + lr];
                b[1] = sV[(8 * kk + 4 + lc) * 72 + 8 * ni + lr];
                mma_tf32(o[ni], a, b);
            }
        }
        __syncthreads();
        if (j + 2 <= jmax) ATTN_ISSUE(j & 1, j + 2);
        cp_commit();
    }

    // epilogue: att layout [B, T, H*D], pre-rounded to tf32
    const float il0 = 1.f / l0, il1 = 1.f / l1;
    const int b_ = bh >> 4, h = bh & 15;
    float* Ob = g_att + ((size_t)b_ * T_ + (size_t)qi * 128 + r_warp) * (H_ * D_) + h * D_;
#pragma unroll
    for (int ni = 0; ni < 8; ni++) {
        int c = 8 * ni + 2 * lc;
        float2 v0 = { __uint_as_float(f2tf(o[ni][0] * il0)),
                      __uint_as_float(f2tf(o[ni][1] * il0)) };
        float2 v1 = { __uint_as_float(f2tf(o[ni][2] * il1)),
                      __uint_as_float(f2tf(o[ni][3] * il1)) };
        *reinterpret_cast<float2*>(&Ob[(size_t)lr * (H_ * D_) + c]) = v0;
        *reinterpret_cast<float2*>(&Ob[(size_t)(lr + 8) * (H_ * D_) + c]) = v1;
    }
}

// ---------------------------------------------------------------------------
// Kernel 3: output projection + bias from pre-rounded g_att/g_wp.
// Same tiling/pipeline as kernel 1. Grid (64, 8).
// ---------------------------------------------------------------------------
__global__ __launch_bounds__(256, 2) void proj_mma_kernel(
    const float* __restrict__ bias,
    float* __restrict__ C) {
    extern __shared__ uint32_t dyn[];

    const int mt = blockIdx.x;   // 0..63
    const int nt = blockIdx.y;   // 0..7
    const int tid = threadIdx.x;
    const int w = tid >> 5, lane = tid & 31;
    const int wm = w >> 2, wn = w & 3;
    const int m0 = wm * 64, n0 = wn * 32;
    const int lr = lane >> 2, lc = lane & 3;

    const float* Ab = g_att + (size_t)mt * 128 * E_;
    const float* Bw = g_wp + (size_t)nt * 128;

    float acc[4][4][4] = {};

#define PROJ_ISSUE(stg, k0)                                                       \
    {                                                                             \
        uint32_t* sA_ = dyn + (stg) * GEMM_STAGE_W;                               \
        uint32_t* sB_ = sA_ + 4608;                                               \
        _Pragma("unroll")                                                         \
        for (int l = 0; l < 4; l++) {                                             \
            int idx = tid + l * 256;                                              \
            { int r = idx >> 3, f = (idx & 7) * 4;                                \
              cp16(smem_u32(&sA_[r * 36 + f]), Ab + (size_t)r * E_ + (k0) + f); } \
            { int r = idx >> 5, c = (idx & 31) * 4;                               \
              cp16(smem_u32(&sB_[r * 136 + c]),                                   \
                   Bw + (size_t)((k0) + r) * E_ + c); }                           \
        }                                                                         \
    }

    PROJ_ISSUE(0, 0); cp_commit();
    PROJ_ISSUE(1, 32); cp_commit();

    for (int it = 0; it < 32; it++) {
        cp_wait1();
        __syncthreads();
        const uint32_t* sA = dyn + (it & 1) * GEMM_STAGE_W;
        const uint32_t* sB = sA + 4608;
#pragma unroll
        for (int ks = 0; ks < 32; ks += 8) {
            uint32_t a[4][4], b[4][2];
#pragma unroll
            for (int mi = 0; mi < 4; mi++) {
                int r0 = m0 + 16 * mi + lr;
                a[mi][0] = sA[r0 * 36 + ks + lc];
                a[mi][1] = sA[(r0 + 8) * 36 + ks + lc];
                a[mi][2] = sA[r0 * 36 + ks + 4 + lc];
                a[mi][3] = sA[(r0 + 8) * 36 + ks + 4 + lc];
            }
#pragma unroll
            for (int ni = 0; ni < 4; ni++) {
                int cb = n0 + 8 * ni + lr;
                b[ni][0] = sB[(ks + lc) * 136 + cb];
                b[ni][1] = sB[(ks + 4 + lc) * 136 + cb];
            }
#pragma unroll
            for (int mi = 0; mi < 4; mi++)
#pragma unroll
                for (int ni = 0; ni < 4; ni++) mma_tf32(acc[mi][ni], a[mi], b[ni]);
        }
        __syncthreads();
        if (it + 2 < 32) PROJ_ISSUE(it & 1, (it + 2) * 32);
        cp_commit();
    }

    float* Cb = C + (size_t)mt * 128 * E_ + (size_t)nt * 128;
#pragma unroll
    for (int mi = 0; mi < 4; mi++)
#pragma unroll
        for (int ni = 0; ni < 4; ni++) {
            int col = n0 + 8 * ni + 2 * lc;
            float b0 = bias[nt * 128 + col], b1 = bias[nt * 128 + col + 1];
            int row0 = m0 + 16 * mi + lr;
            float2 v0 = { acc[mi][ni][0] + b0, acc[mi][ni][1] + b1 };
            float2 v1 = { acc[mi][ni][2] + b0, acc[mi][ni][3] + b1 };
            *reinterpret_cast<float2*>(Cb + (size_t)row0 * E_ + col) = v0;
            *reinterpret_cast<float2*>(Cb + (size_t)(row0 + 8) * E_ + col) = v1;
        }
}

// ---------------------------------------------------------------------------
extern "C" void kernel_launch(void* const* d_in, const int* in_sizes, int n_in,
                              void* d_out, int out_size) {
    const float* x     = (const float*)d_in[0];
    const float* Wq    = (const float*)d_in[1];
    const float* Wk    = (const float*)d_in[2];
    const float* Wv    = (const float*)d_in[3];
    const float* Wproj = (const float*)d_in[4];
    const float* bproj = (const float*)d_in[5];
    float* out = (float*)d_out;

    float *dg_x, *dg_w, *dg_wp;
    cudaGetSymbolAddress((void**)&dg_x, g_x);
    cudaGetSymbolAddress((void**)&dg_w, g_w);
    cudaGetSymbolAddress((void**)&dg_wp, g_wp);

    const int nx4 = B_ * T_ * E_ / 4;           // 2097152
    const int nw4 = H_ * E_ * D_ / 4;           // 262144
    const int np4 = E_ * E_ / 4;                // 262144
    prep_kernel<<<(nx4 + 255) / 256, 256>>>((const float4*)x, (float4*)dg_x, nx4);
    prep_kernel<<<(nw4 + 255) / 256, 256>>>((const float4*)Wq, (float4*)dg_w, nw4);
    prep_kernel<<<(nw4 + 255) / 256, 256>>>((const float4*)Wk, (float4*)(dg_w + (size_t)H_ * E_ * D_), nw4);
    prep_kernel<<<(nw4 + 255) / 256, 256>>>((const float4*)Wv, (float4*)(dg_w + (size_t)2 * H_ * E_ * D_), nw4);
    prep_kernel<<<(np4 + 255) / 256, 256>>>((const float4*)Wproj, (float4*)dg_wp, np4);

    const int dyn_smem = 2 * GEMM_STAGE_W * (int)sizeof(uint32_t);  // 71680
    cudaFuncSetAttribute(qkv_mma_kernel, cudaFuncAttributeMaxDynamicSharedMemorySize, dyn_smem);
    cudaFuncSetAttribute(attn_mma_kernel, cudaFuncAttributeMaxDynamicSharedMemorySize, dyn_smem);
    cudaFuncSetAttribute(proj_mma_kernel, cudaFuncAttributeMaxDynamicSharedMemorySize, dyn_smem);

    qkv_mma_kernel<<<dim3(64, 24), 256, dyn_smem>>>();
    attn_mma_kernel<<<dim3(16, 64), 256, dyn_smem>>>();
    proj_mma_kernel<<<dim3(64, 8), 256, dyn_smem>>>(bproj, out);
}